// round 1
// baseline (speedup 1.0000x reference)
#include <cuda_runtime.h>

#define EMB    1024
#define HEADD  64
#define BATCH  4
#define SEQ    4096
#define NROWS  (BATCH * SEQ)          // 16384
#define NQT    (SEQ / 64)             // 64 query tiles per batch
#define NITEM  (NQT * BATCH)          // 256 work items

// Scratch (no cudaMalloc allowed): q/k/v projections, 4 MB each
__device__ float g_q[NROWS * HEADD];
__device__ float g_k[NROWS * HEADD];
__device__ float g_v[NROWS * HEADD];
__device__ int   g_ctr;

__global__ void reset_ctr_kernel() { g_ctr = 0; }

// ---------------------------------------------------------------------------
// QKV projection: out[16384 x 64] = x[16384 x 1024] @ W[1024 x 64] + b
// grid (NROWS/64, 3), block 256 (16x16 logical), 4x4 register tile, K-chunk 32
// ---------------------------------------------------------------------------
__global__ __launch_bounds__(256) void qkv_kernel(
    const float* __restrict__ x,
    const float* __restrict__ Wq, const float* __restrict__ bq,
    const float* __restrict__ Wk, const float* __restrict__ bk,
    const float* __restrict__ Wv, const float* __restrict__ bv)
{
    const float* W; const float* bias; float* out;
    const int sel = blockIdx.y;
    if (sel == 0)      { W = Wq; bias = bq; out = g_q; }
    else if (sel == 1) { W = Wk; bias = bk; out = g_k; }
    else               { W = Wv; bias = bv; out = g_v; }

    __shared__ float xs[64 * 32];   // [row][e], stride 32 (broadcast reads -> no pad)
    __shared__ float ws[32 * 68];   // [e][col], stride 68 (16B-aligned float4 reads)

    const int t  = threadIdx.x;
    const int tx = t & 15;
    const int ty = t >> 4;
    const int row0 = blockIdx.x * 64;

    float acc[4][4] = {};

    for (int e0 = 0; e0 < EMB; e0 += 32) {
        // load x tile 64x32 (512 float4s)
        #pragma unroll
        for (int n4 = t; n4 < 512; n4 += 256) {
            const int r = n4 >> 3, c = (n4 & 7) << 2;
            const float4 v = *(const float4*)(x + (row0 + r) * EMB + e0 + c);
            float* d = &xs[r * 32 + c];
            d[0] = v.x; d[1] = v.y; d[2] = v.z; d[3] = v.w;
        }
        // load W tile 32x64
        #pragma unroll
        for (int n4 = t; n4 < 512; n4 += 256) {
            const int r = n4 >> 4, c = (n4 & 15) << 2;
            const float4 v = *(const float4*)(W + (e0 + r) * HEADD + c);
            float* d = &ws[r * 68 + c];
            d[0] = v.x; d[1] = v.y; d[2] = v.z; d[3] = v.w;
        }
        __syncthreads();

        #pragma unroll
        for (int e = 0; e < 32; e += 4) {
            float a[4][4], b[4][4];
            #pragma unroll
            for (int i = 0; i < 4; i++) {
                const float4 v = *(const float4*)&xs[(4 * ty + i) * 32 + e];
                a[i][0] = v.x; a[i][1] = v.y; a[i][2] = v.z; a[i][3] = v.w;
            }
            #pragma unroll
            for (int q = 0; q < 4; q++) {
                const float4 v = *(const float4*)&ws[(e + q) * 68 + 4 * tx];
                b[q][0] = v.x; b[q][1] = v.y; b[q][2] = v.z; b[q][3] = v.w;
            }
            #pragma unroll
            for (int i = 0; i < 4; i++)
                #pragma unroll
                for (int j = 0; j < 4; j++)
                    #pragma unroll
                    for (int q = 0; q < 4; q++)
                        acc[i][j] += a[i][q] * b[q][j];
        }
        __syncthreads();
    }

    #pragma unroll
    for (int i = 0; i < 4; i++) {
        const int row = row0 + 4 * ty + i;
        #pragma unroll
        for (int j = 0; j < 4; j++)
            out[row * HEADD + 4 * tx + j] = acc[i][j] + bias[4 * tx + j];
    }
}

// ---------------------------------------------------------------------------
// Flash attention, causal. 64-query tiles, 64-key tiles, online softmax.
// Work items pulled from an atomic queue, heaviest q-tiles first.
// Dynamic smem layout (floats):
//   Qs  [64][64]  at 0       (stride 64)
//   KsT [64][68]  at 4096    (transposed: [e][k], stride 68)
//   Vs  [64][64]  at 8448    (stride 64)
//   Ps  [64][64]  at 12544   (stride 64)
// total 16640 floats = 66560 bytes
// ---------------------------------------------------------------------------
#define SM_QS  0
#define SM_KT  4096
#define SM_VS  8448
#define SM_PS  12544
#define SMEM_FLOATS 16640

__global__ __launch_bounds__(256) void attn_kernel(float* __restrict__ out)
{
    extern __shared__ float sm[];
    float* Qs  = sm + SM_QS;
    float* KsT = sm + SM_KT;
    float* Vs  = sm + SM_VS;
    float* Ps  = sm + SM_PS;

    const int t  = threadIdx.x;
    const int tx = t & 15;
    const int ty = t >> 4;

    __shared__ int s_item;

    for (;;) {
        if (t == 0) s_item = atomicAdd(&g_ctr, 1);
        __syncthreads();
        const int item = s_item;
        if (item >= NITEM) return;

        const int qt = (NQT - 1) - (item >> 2);   // heavy tiles first
        const int b  = item & 3;

        const float* qp    = g_q + (b * SEQ + qt * 64) * HEADD;
        const float* kbase = g_k + b * SEQ * HEADD;
        const float* vbase = g_v + b * SEQ * HEADD;

        // load Q tile 64x64
        #pragma unroll
        for (int n4 = t; n4 < 1024; n4 += 256) {
            const int r = n4 >> 4, c = (n4 & 15) << 2;
            const float4 v = *(const float4*)(qp + r * HEADD + c);
            float* d = &Qs[r * 64 + c];
            d[0] = v.x; d[1] = v.y; d[2] = v.z; d[3] = v.w;
        }

        float m[4], l[4], o[4][4];
        #pragma unroll
        for (int i = 0; i < 4; i++) {
            m[i] = -1e30f; l[i] = 0.f;
            #pragma unroll
            for (int j = 0; j < 4; j++) o[i][j] = 0.f;
        }

        const int nkt = qt + 1;
        for (int kt = 0; kt < nkt; kt++) {
            __syncthreads();   // previous PV / Q-load done before overwriting tiles
            const float* kp = kbase + kt * 64 * HEADD;
            const float* vp = vbase + kt * 64 * HEADD;
            #pragma unroll
            for (int n4 = t; n4 < 1024; n4 += 256) {
                const int r = n4 >> 4, c = (n4 & 15) << 2;
                const float4 kv = *(const float4*)(kp + r * HEADD + c);
                KsT[(c + 0) * 68 + r] = kv.x;
                KsT[(c + 1) * 68 + r] = kv.y;
                KsT[(c + 2) * 68 + r] = kv.z;
                KsT[(c + 3) * 68 + r] = kv.w;
                const float4 vv = *(const float4*)(vp + r * HEADD + c);
                float* d = &Vs[r * 64 + c];
                d[0] = vv.x; d[1] = vv.y; d[2] = vv.z; d[3] = vv.w;
            }
            __syncthreads();

            // scores: s[4q][4k] = Q(4 rows) . K(4 cols)
            float s[4][4] = {};
            #pragma unroll
            for (int e = 0; e < 64; e += 4) {
                float a[4][4], bb[4][4];
                #pragma unroll
                for (int i = 0; i < 4; i++) {
                    const float4 v = *(const float4*)&Qs[(4 * ty + i) * 64 + e];
                    a[i][0] = v.x; a[i][1] = v.y; a[i][2] = v.z; a[i][3] = v.w;
                }
                #pragma unroll
                for (int q = 0; q < 4; q++) {
                    const float4 v = *(const float4*)&KsT[(e + q) * 68 + 4 * tx];
                    bb[q][0] = v.x; bb[q][1] = v.y; bb[q][2] = v.z; bb[q][3] = v.w;
                }
                #pragma unroll
                for (int i = 0; i < 4; i++)
                    #pragma unroll
                    for (int j = 0; j < 4; j++)
                        #pragma unroll
                        for (int q = 0; q < 4; q++)
                            s[i][j] += a[i][q] * bb[q][j];
            }

            // scale + causal mask + online softmax update
            #pragma unroll
            for (int i = 0; i < 4; i++) {
                const int qg = qt * 64 + 4 * ty + i;
                #pragma unroll
                for (int j = 0; j < 4; j++) {
                    const int kg = kt * 64 + 4 * tx + j;
                    float v = s[i][j] * 0.125f;   // 1/sqrt(64)
                    if (kg > qg) v = -1e30f;
                    s[i][j] = v;
                }
                float mx = fmaxf(fmaxf(s[i][0], s[i][1]), fmaxf(s[i][2], s[i][3]));
                mx = fmaxf(mx, __shfl_xor_sync(0xffffffffu, mx, 1));
                mx = fmaxf(mx, __shfl_xor_sync(0xffffffffu, mx, 2));
                mx = fmaxf(mx, __shfl_xor_sync(0xffffffffu, mx, 4));
                mx = fmaxf(mx, __shfl_xor_sync(0xffffffffu, mx, 8));
                const float mnew = fmaxf(m[i], mx);
                const float corr = __expf(m[i] - mnew);
                m[i] = mnew;
                float rs = 0.f;
                #pragma unroll
                for (int j = 0; j < 4; j++) {
                    const float p = __expf(s[i][j] - mnew);
                    s[i][j] = p;
                    rs += p;
                }
                rs += __shfl_xor_sync(0xffffffffu, rs, 1);
                rs += __shfl_xor_sync(0xffffffffu, rs, 2);
                rs += __shfl_xor_sync(0xffffffffu, rs, 4);
                rs += __shfl_xor_sync(0xffffffffu, rs, 8);
                l[i] = l[i] * corr + rs;
                #pragma unroll
                for (int j = 0; j < 4; j++) o[i][j] *= corr;
                *(float4*)&Ps[(4 * ty + i) * 64 + 4 * tx] =
                    make_float4(s[i][0], s[i][1], s[i][2], s[i][3]);
            }
            __syncwarp();   // Ps exchange is intra-warp (16 tx lanes share a row)

            // PV: o[4q][4d] += P(4 rows, all k) * V(all k, 4 cols)
            #pragma unroll
            for (int k = 0; k < 64; k += 4) {
                float p[4][4], vv[4][4];
                #pragma unroll
                for (int i = 0; i < 4; i++) {
                    const float4 v = *(const float4*)&Ps[(4 * ty + i) * 64 + k];
                    p[i][0] = v.x; p[i][1] = v.y; p[i][2] = v.z; p[i][3] = v.w;
                }
                #pragma unroll
                for (int q = 0; q < 4; q++) {
                    const float4 v = *(const float4*)&Vs[(k + q) * 64 + 4 * tx];
                    vv[q][0] = v.x; vv[q][1] = v.y; vv[q][2] = v.z; vv[q][3] = v.w;
                }
                #pragma unroll
                for (int i = 0; i < 4; i++)
                    #pragma unroll
                    for (int j = 0; j < 4; j++)
                        #pragma unroll
                        for (int q = 0; q < 4; q++)
                            o[i][j] += p[i][q] * vv[q][j];
            }
        }

        // epilogue: normalize and store
        #pragma unroll
        for (int i = 0; i < 4; i++) {
            const float inv = 1.0f / l[i];
            const int row = b * SEQ + qt * 64 + 4 * ty + i;
            *(float4*)&out[row * HEADD + 4 * tx] =
                make_float4(o[i][0] * inv, o[i][1] * inv, o[i][2] * inv, o[i][3] * inv);
        }
        __syncthreads();   // all reads of this item's tiles done before next item
    }
}

// ---------------------------------------------------------------------------
extern "C" void kernel_launch(void* const* d_in, const int* in_sizes, int n_in,
                              void* d_out, int out_size)
{
    const float* x  = (const float*)d_in[0];
    const float* Wq = (const float*)d_in[1];
    const float* bq = (const float*)d_in[2];
    const float* Wk = (const float*)d_in[3];
    const float* bk = (const float*)d_in[4];
    const float* Wv = (const float*)d_in[5];
    const float* bv = (const float*)d_in[6];
    float* out = (float*)d_out;

    reset_ctr_kernel<<<1, 1>>>();

    qkv_kernel<<<dim3(NROWS / 64, 3), 256>>>(x, Wq, bq, Wk, bk, Wv, bv);

    const size_t smem = SMEM_FLOATS * sizeof(float);   // 66560 B
    cudaFuncSetAttribute(attn_kernel,
                         cudaFuncAttributeMaxDynamicSharedMemorySize, (int)smem);
    attn_kernel<<<448, 256, smem>>>(out);
}

// round 4
// speedup vs baseline: 3.6003x; 3.6003x over previous
#include <cuda_runtime.h>
#include <cuda_bf16.h>
#include <cstdint>

#define EMB    1024
#define HEADD  64
#define BATCH  4
#define SEQ    4096
#define NROWS  (BATCH * SEQ)      // 16384
#define NQT    64                 // 64-row q tiles per batch
#define NJ     160                // chunk items per batch
#define NITEM  (NJ * BATCH)       // 640
#define PART_STRIDE 4224          // 64*64 O + 64 m + 64 l

// split bf16 planes of Q, K (row-major [row][dim]) and V (transposed [b][dim][seq])
__device__ __align__(16) __nv_bfloat16 g_qh[NROWS * HEADD], g_ql[NROWS * HEADD];
__device__ __align__(16) __nv_bfloat16 g_kh[NROWS * HEADD], g_kl[NROWS * HEADD];
__device__ __align__(16) __nv_bfloat16 g_vth[NROWS * HEADD], g_vtl[NROWS * HEADD];
__device__ __align__(16) float g_part[(size_t)NITEM * PART_STRIDE];
__device__ int g_ctr;

__global__ void reset_ctr_kernel() { g_ctr = 0; }

// ---------------------------------------------------------------------------
// helpers
// ---------------------------------------------------------------------------
__device__ __forceinline__ uint32_t pack2(float a, float b) {
    __nv_bfloat162 t = __floats2bfloat162_rn(a, b);
    return *reinterpret_cast<uint32_t*>(&t);
}
__device__ __forceinline__ void splitf(float v, float& h, float& l) {
    h = __bfloat162float(__float2bfloat16(v));
    l = v - h;
}
__device__ __forceinline__ void mma16816(float* d, const uint32_t* a,
                                         uint32_t b0, uint32_t b1) {
    asm volatile(
        "mma.sync.aligned.m16n8k16.row.col.f32.bf16.bf16.f32 "
        "{%0,%1,%2,%3}, {%4,%5,%6,%7}, {%8,%9}, {%0,%1,%2,%3};\n"
        : "+f"(d[0]), "+f"(d[1]), "+f"(d[2]), "+f"(d[3])
        : "r"(a[0]), "r"(a[1]), "r"(a[2]), "r"(a[3]), "r"(b0), "r"(b1));
}

// ---------------------------------------------------------------------------
// QKV projection: [16384 x 1024] @ [1024 x 64] + b, bf16x2 split MMA.
// grid (128, 3), block 256 (8 warps, warp tile 16x64). BK=32.
// Writes Q/K as hi/lo planes [row][dim]; V as hi/lo planes transposed
// [b][dim][seq] so attention's PV B-operand is a coalesced copy.
// ---------------------------------------------------------------------------
__global__ __launch_bounds__(256) void qkv_kernel(
    const float* __restrict__ x,
    const float* __restrict__ Wq, const float* __restrict__ bq,
    const float* __restrict__ Wk, const float* __restrict__ bk,
    const float* __restrict__ Wv, const float* __restrict__ bv)
{
    const int sel = blockIdx.y;
    const float* W    = sel == 0 ? Wq : (sel == 1 ? Wk : Wv);
    const float* bias = sel == 0 ? bq : (sel == 1 ? bk : bv);

    __shared__ __align__(16) __nv_bfloat16 Xh[128 * 40], Xl[128 * 40];
    __shared__ __align__(16) __nv_bfloat16 Wth[64 * 40], Wtl[64 * 40];

    const int t = threadIdx.x, w = t >> 5, lane = t & 31;
    const int row0 = blockIdx.x * 128;

    float acc[8][4];
    #pragma unroll
    for (int n = 0; n < 8; n++)
        #pragma unroll
        for (int c = 0; c < 4; c++) acc[n][c] = 0.f;

    for (int k0 = 0; k0 < EMB; k0 += 32) {
        __syncthreads();
        // X tile 128x32 fp32 -> split hi/lo bf16 (row stride 40 bf16)
        #pragma unroll
        for (int i = 0; i < 4; i++) {
            const int idx4 = t + 256 * i;
            const int r = idx4 >> 3, c = (idx4 & 7) << 2;
            const float4 v = *(const float4*)(x + (size_t)(row0 + r) * EMB + k0 + c);
            float h0, l0, h1, l1, h2, l2, h3, l3;
            splitf(v.x, h0, l0); splitf(v.y, h1, l1);
            splitf(v.z, h2, l2); splitf(v.w, h3, l3);
            uint32_t* dh = (uint32_t*)Xh + r * 20 + (c >> 1);
            uint32_t* dl = (uint32_t*)Xl + r * 20 + (c >> 1);
            dh[0] = pack2(h0, h1); dh[1] = pack2(h2, h3);
            dl[0] = pack2(l0, l1); dl[1] = pack2(l2, l3);
        }
        // W tile 32x64 fp32 -> transposed hi/lo Wt[n][k] (row stride 40)
        #pragma unroll
        for (int i = 0; i < 8; i++) {
            const int idx = t + 256 * i;
            const int k = idx >> 6, n = idx & 63;
            const float f = W[(size_t)(k0 + k) * HEADD + n];
            float h, l; splitf(f, h, l);
            Wth[n * 40 + k] = __float2bfloat16(h);
            Wtl[n * 40 + k] = __float2bfloat16(l);
        }
        __syncthreads();

        #pragma unroll
        for (int s = 0; s < 2; s++) {
            const int ar = (w << 4) + (lane >> 2);
            const int ac = ((lane & 3) << 1) + (s << 4);
            uint32_t ah[4], al[4];
            ah[0] = *(const uint32_t*)&Xh[ar * 40 + ac];
            ah[1] = *(const uint32_t*)&Xh[(ar + 8) * 40 + ac];
            ah[2] = *(const uint32_t*)&Xh[ar * 40 + ac + 8];
            ah[3] = *(const uint32_t*)&Xh[(ar + 8) * 40 + ac + 8];
            al[0] = *(const uint32_t*)&Xl[ar * 40 + ac];
            al[1] = *(const uint32_t*)&Xl[(ar + 8) * 40 + ac];
            al[2] = *(const uint32_t*)&Xl[ar * 40 + ac + 8];
            al[3] = *(const uint32_t*)&Xl[(ar + 8) * 40 + ac + 8];
            #pragma unroll
            for (int n = 0; n < 8; n++) {
                const int br = (n << 3) + (lane >> 2);
                const uint32_t bh0 = *(const uint32_t*)&Wth[br * 40 + ac];
                const uint32_t bh1 = *(const uint32_t*)&Wth[br * 40 + ac + 8];
                const uint32_t bl0 = *(const uint32_t*)&Wtl[br * 40 + ac];
                const uint32_t bl1 = *(const uint32_t*)&Wtl[br * 40 + ac + 8];
                mma16816(acc[n], ah, bh0, bh1);
                mma16816(acc[n], ah, bl0, bl1);
                mma16816(acc[n], al, bh0, bh1);
            }
        }
    }

    // epilogue: +bias, split, store
    const int r0 = row0 + (w << 4) + (lane >> 2);
    const int r1 = r0 + 8;
    #pragma unroll
    for (int n = 0; n < 8; n++) {
        const int col0 = (n << 3) + ((lane & 3) << 1);
        const float b0 = bias[col0], b1 = bias[col0 + 1];
        const float v00 = acc[n][0] + b0, v01 = acc[n][1] + b1;
        const float v10 = acc[n][2] + b0, v11 = acc[n][3] + b1;
        float h00, l00, h01, l01, h10, l10, h11, l11;
        splitf(v00, h00, l00); splitf(v01, h01, l01);
        splitf(v10, h10, l10); splitf(v11, h11, l11);
        if (sel < 2) {
            __nv_bfloat16* oh = sel ? g_kh : g_qh;
            __nv_bfloat16* ol = sel ? g_kl : g_ql;
            ((uint32_t*)oh)[r0 * 32 + (col0 >> 1)] = pack2(h00, h01);
            ((uint32_t*)oh)[r1 * 32 + (col0 >> 1)] = pack2(h10, h11);
            ((uint32_t*)ol)[r0 * 32 + (col0 >> 1)] = pack2(l00, l01);
            ((uint32_t*)ol)[r1 * 32 + (col0 >> 1)] = pack2(l10, l11);
        } else {
            const int b0i = r0 >> 12, s0 = r0 & 4095;
            const int b1i = r1 >> 12, s1 = r1 & 4095;
            g_vth[((size_t)b0i * 64 + col0) * SEQ + s0]     = __float2bfloat16(h00);
            g_vth[((size_t)b0i * 64 + col0 + 1) * SEQ + s0] = __float2bfloat16(h01);
            g_vth[((size_t)b1i * 64 + col0) * SEQ + s1]     = __float2bfloat16(h10);
            g_vth[((size_t)b1i * 64 + col0 + 1) * SEQ + s1] = __float2bfloat16(h11);
            g_vtl[((size_t)b0i * 64 + col0) * SEQ + s0]     = __float2bfloat16(l00);
            g_vtl[((size_t)b0i * 64 + col0 + 1) * SEQ + s0] = __float2bfloat16(l01);
            g_vtl[((size_t)b1i * 64 + col0) * SEQ + s1]     = __float2bfloat16(l10);
            g_vtl[((size_t)b1i * 64 + col0 + 1) * SEQ + s1] = __float2bfloat16(l11);
        }
    }
}

// ---------------------------------------------------------------------------
// item decode: per batch, 160 (qt, chunk) items, heavy q-tiles first.
// qt 48-63: 4 chunks, 32-47: 3, 16-31: 2, 0-15: 1. Chunk = 16 k-tiles.
// ---------------------------------------------------------------------------
__device__ __forceinline__ void decode_j(int j, int& qt, int& c) {
    if (j < 64)       { qt = 63 - (j >> 2); c = j & 3; }
    else if (j < 112) { const int r = j - 64;  qt = 47 - r / 3;    c = r % 3; }
    else if (j < 144) { const int r = j - 112; qt = 31 - (r >> 1); c = r & 1; }
    else              { qt = 15 - (j - 144); c = 0; }
}
__device__ __forceinline__ int j_of(int qt, int c) {
    if (qt >= 48) return (63 - qt) * 4 + c;
    if (qt >= 32) return 64 + (47 - qt) * 3 + c;
    if (qt >= 16) return 112 + (31 - qt) * 2 + c;
    return 144 + (15 - qt);
}

// ---------------------------------------------------------------------------
// Flash attention on bf16x2 MMA. Block = 128 threads (4 warps x 16 q-rows).
// Item = (batch, 64-row q-tile, <=16 k-tile chunk); partial (O, m, l) to gmem.
// smem (dyn): Qh Ql Kh Kl Vh Vl, each 64x72 bf16 -> 55296 B.
// ---------------------------------------------------------------------------
__global__ __launch_bounds__(128, 3) void attn_kernel()
{
    extern __shared__ __align__(16) __nv_bfloat16 sm[];
    __nv_bfloat16* Qh = sm;
    __nv_bfloat16* Ql = sm + 64 * 72;
    __nv_bfloat16* Kh = sm + 2 * 64 * 72;
    __nv_bfloat16* Kl = sm + 3 * 64 * 72;
    __nv_bfloat16* Vh = sm + 4 * 64 * 72;
    __nv_bfloat16* Vl = sm + 5 * 64 * 72;
    __shared__ int s_item;

    const int t = threadIdx.x, w = t >> 5, lane = t & 31;

    for (;;) {
        if (t == 0) s_item = atomicAdd(&g_ctr, 1);
        __syncthreads();
        const int item = s_item;
        if (item >= NITEM) return;
        const int j = item >> 2, b = item & 3;
        int qt, c; decode_j(j, qt, c);
        const int kt0 = c * 16;
        const int kt1 = min(kt0 + 16, qt + 1);

        // Q tile (hi/lo) -> smem, stride 72 bf16 (2048 uint32 per plane)
        {
            const uint32_t* sh = (const uint32_t*)g_qh + (size_t)(b * SEQ + qt * 64) * 32;
            const uint32_t* sl = (const uint32_t*)g_ql + (size_t)(b * SEQ + qt * 64) * 32;
            #pragma unroll
            for (int i = 0; i < 16; i++) {
                const int idx = t + 128 * i;
                const int r = idx >> 5, cc = idx & 31;
                ((uint32_t*)Qh)[r * 36 + cc] = sh[r * 32 + cc];
                ((uint32_t*)Ql)[r * 36 + cc] = sl[r * 32 + cc];
            }
        }

        float m0 = -1e30f, m1 = -1e30f, lsum0 = 0.f, lsum1 = 0.f;
        float o[8][4];
        #pragma unroll
        for (int n = 0; n < 8; n++)
            #pragma unroll
            for (int cc = 0; cc < 4; cc++) o[n][cc] = 0.f;

        const int qg0 = qt * 64 + (w << 4) + (lane >> 2);
        const int qg1 = qg0 + 8;

        for (int kt = kt0; kt < kt1; kt++) {
            __syncthreads();
            // K/V tiles: 64 rows x 32 uint32 per plane -> 2048 uint32 each,
            // 128 threads x 16 iterations.  (Round-3 bug: this ran i<8 and
            // left rows 32-63 uninitialized -> NaN.)
            {
                const uint32_t* sh = (const uint32_t*)g_kh + (size_t)(b * SEQ + kt * 64) * 32;
                const uint32_t* sl = (const uint32_t*)g_kl + (size_t)(b * SEQ + kt * 64) * 32;
                const uint32_t* vh = (const uint32_t*)g_vth + (size_t)b * 64 * 2048 + kt * 32;
                const uint32_t* vl = (const uint32_t*)g_vtl + (size_t)b * 64 * 2048 + kt * 32;
                #pragma unroll
                for (int i = 0; i < 16; i++) {
                    const int idx = t + 128 * i;
                    const int r = idx >> 5, cc = idx & 31;
                    ((uint32_t*)Kh)[r * 36 + cc] = sh[r * 32 + cc];
                    ((uint32_t*)Kl)[r * 36 + cc] = sl[r * 32 + cc];
                    ((uint32_t*)Vh)[r * 36 + cc] = vh[(size_t)r * 2048 + cc];
                    ((uint32_t*)Vl)[r * 36 + cc] = vl[(size_t)r * 2048 + cc];
                }
            }
            __syncthreads();

            // scores S = Q K^T (warp tile 16x64)
            float s[8][4];
            #pragma unroll
            for (int n = 0; n < 8; n++)
                #pragma unroll
                for (int cc = 0; cc < 4; cc++) s[n][cc] = 0.f;
            #pragma unroll
            for (int ss = 0; ss < 4; ss++) {
                const int ar = (w << 4) + (lane >> 2);
                const int ac = ((lane & 3) << 1) + (ss << 4);
                uint32_t ah[4], al[4];
                ah[0] = *(const uint32_t*)&Qh[ar * 72 + ac];
                ah[1] = *(const uint32_t*)&Qh[(ar + 8) * 72 + ac];
                ah[2] = *(const uint32_t*)&Qh[ar * 72 + ac + 8];
                ah[3] = *(const uint32_t*)&Qh[(ar + 8) * 72 + ac + 8];
                al[0] = *(const uint32_t*)&Ql[ar * 72 + ac];
                al[1] = *(const uint32_t*)&Ql[(ar + 8) * 72 + ac];
                al[2] = *(const uint32_t*)&Ql[ar * 72 + ac + 8];
                al[3] = *(const uint32_t*)&Ql[(ar + 8) * 72 + ac + 8];
                #pragma unroll
                for (int n = 0; n < 8; n++) {
                    const int br = (n << 3) + (lane >> 2);
                    const uint32_t bh0 = *(const uint32_t*)&Kh[br * 72 + ac];
                    const uint32_t bh1 = *(const uint32_t*)&Kh[br * 72 + ac + 8];
                    const uint32_t bl0 = *(const uint32_t*)&Kl[br * 72 + ac];
                    const uint32_t bl1 = *(const uint32_t*)&Kl[br * 72 + ac + 8];
                    mma16816(s[n], ah, bh0, bh1);
                    mma16816(s[n], ah, bl0, bl1);
                    mma16816(s[n], al, bh0, bh1);
                }
            }

            // softmax (online, on fragments)
            const bool diag = (kt == qt);
            float mx0 = -1e30f, mx1 = -1e30f;
            #pragma unroll
            for (int n = 0; n < 8; n++) {
                const int kg = kt * 64 + (n << 3) + ((lane & 3) << 1);
                float v0 = s[n][0] * 0.125f, v1 = s[n][1] * 0.125f;
                float v2 = s[n][2] * 0.125f, v3 = s[n][3] * 0.125f;
                if (diag) {
                    if (kg     > qg0) v0 = -1e30f;
                    if (kg + 1 > qg0) v1 = -1e30f;
                    if (kg     > qg1) v2 = -1e30f;
                    if (kg + 1 > qg1) v3 = -1e30f;
                }
                s[n][0] = v0; s[n][1] = v1; s[n][2] = v2; s[n][3] = v3;
                mx0 = fmaxf(mx0, fmaxf(v0, v1));
                mx1 = fmaxf(mx1, fmaxf(v2, v3));
            }
            mx0 = fmaxf(mx0, __shfl_xor_sync(0xffffffffu, mx0, 1));
            mx0 = fmaxf(mx0, __shfl_xor_sync(0xffffffffu, mx0, 2));
            mx1 = fmaxf(mx1, __shfl_xor_sync(0xffffffffu, mx1, 1));
            mx1 = fmaxf(mx1, __shfl_xor_sync(0xffffffffu, mx1, 2));
            const float mn0 = fmaxf(m0, mx0), mn1 = fmaxf(m1, mx1);
            const float cr0 = __expf(m0 - mn0), cr1 = __expf(m1 - mn1);
            m0 = mn0; m1 = mn1;

            float rs0 = 0.f, rs1 = 0.f;
            uint32_t pah[4][4], pal[4][4];
            #pragma unroll
            for (int n = 0; n < 8; n++) {
                const float p0 = __expf(s[n][0] - mn0), p1 = __expf(s[n][1] - mn0);
                const float p2 = __expf(s[n][2] - mn1), p3 = __expf(s[n][3] - mn1);
                rs0 += p0 + p1; rs1 += p2 + p3;
                float h0, l0, h1, l1, h2, l2, h3, l3;
                splitf(p0, h0, l0); splitf(p1, h1, l1);
                splitf(p2, h2, l2); splitf(p3, h3, l3);
                const int ss = n >> 1, hf = (n & 1) << 1;
                pah[ss][hf]     = pack2(h0, h1);
                pah[ss][hf + 1] = pack2(h2, h3);
                pal[ss][hf]     = pack2(l0, l1);
                pal[ss][hf + 1] = pack2(l2, l3);
            }
            rs0 += __shfl_xor_sync(0xffffffffu, rs0, 1);
            rs0 += __shfl_xor_sync(0xffffffffu, rs0, 2);
            rs1 += __shfl_xor_sync(0xffffffffu, rs1, 1);
            rs1 += __shfl_xor_sync(0xffffffffu, rs1, 2);
            lsum0 = lsum0 * cr0 + rs0;
            lsum1 = lsum1 * cr1 + rs1;
            #pragma unroll
            for (int n = 0; n < 8; n++) {
                o[n][0] *= cr0; o[n][1] *= cr0;
                o[n][2] *= cr1; o[n][3] *= cr1;
            }

            // O += P V  (A-frags = repacked P, B from transposed V tile)
            #pragma unroll
            for (int ss = 0; ss < 4; ss++) {
                const int bc = ((lane & 3) << 1) + (ss << 4);
                #pragma unroll
                for (int n = 0; n < 8; n++) {
                    const int br = (n << 3) + (lane >> 2);
                    const uint32_t bh0 = *(const uint32_t*)&Vh[br * 72 + bc];
                    const uint32_t bh1 = *(const uint32_t*)&Vh[br * 72 + bc + 8];
                    const uint32_t bl0 = *(const uint32_t*)&Vl[br * 72 + bc];
                    const uint32_t bl1 = *(const uint32_t*)&Vl[br * 72 + bc + 8];
                    mma16816(o[n], pah[ss], bh0, bh1);
                    mma16816(o[n], pah[ss], bl0, bl1);
                    mma16816(o[n], pal[ss], bh0, bh1);
                }
            }
        }

        // write partial (unnormalized O, m, l)
        float* P = g_part + (size_t)item * PART_STRIDE;
        const int r0 = (w << 4) + (lane >> 2), r1 = r0 + 8;
        #pragma unroll
        for (int n = 0; n < 8; n++) {
            const int col = (n << 3) + ((lane & 3) << 1);
            *(float2*)&P[r0 * 64 + col] = make_float2(o[n][0], o[n][1]);
            *(float2*)&P[r1 * 64 + col] = make_float2(o[n][2], o[n][3]);
        }
        if ((lane & 3) == 0) {
            P[4096 + r0] = m0; P[4096 + r1] = m1;
            P[4160 + r0] = lsum0; P[4160 + r1] = lsum1;
        }
    }
}

// ---------------------------------------------------------------------------
// combine: per (b, qt), merge <=4 chunk partials, normalize, write out.
// ---------------------------------------------------------------------------
__global__ __launch_bounds__(256) void combine_kernel(float* __restrict__ out)
{
    const int bq = blockIdx.x;
    const int b = bq & 3, qt = bq >> 2;
    const int C = (qt >> 4) + 1;
    const int t = threadIdx.x;
    const int row = t >> 2, d0 = (t & 3) << 4;

    int slot[4]; float mc[4], lc[4];
    #pragma unroll
    for (int c = 0; c < 4; c++) {
        if (c < C) {
            slot[c] = (j_of(qt, c) << 2) | b;
            mc[c] = g_part[(size_t)slot[c] * PART_STRIDE + 4096 + row];
            lc[c] = g_part[(size_t)slot[c] * PART_STRIDE + 4160 + row];
        }
    }
    float ms = -1e30f;
    for (int c = 0; c < C; c++) ms = fmaxf(ms, mc[c]);
    float wt[4], denom = 0.f;
    for (int c = 0; c < C; c++) { wt[c] = __expf(mc[c] - ms); denom += wt[c] * lc[c]; }
    const float inv = 1.0f / denom;

    const size_t orow = (size_t)(b * SEQ + qt * 64 + row) * HEADD;
    #pragma unroll
    for (int d4 = 0; d4 < 16; d4 += 4) {
        float4 a = make_float4(0.f, 0.f, 0.f, 0.f);
        for (int c = 0; c < C; c++) {
            const float4 v = *(const float4*)&g_part[(size_t)slot[c] * PART_STRIDE
                                                     + row * 64 + d0 + d4];
            a.x += wt[c] * v.x; a.y += wt[c] * v.y;
            a.z += wt[c] * v.z; a.w += wt[c] * v.w;
        }
        *(float4*)&out[orow + d0 + d4] =
            make_float4(a.x * inv, a.y * inv, a.z * inv, a.w * inv);
    }
}

// ---------------------------------------------------------------------------
extern "C" void kernel_launch(void* const* d_in, const int* in_sizes, int n_in,
                              void* d_out, int out_size)
{
    const float* x  = (const float*)d_in[0];
    const float* Wq = (const float*)d_in[1];
    const float* bq = (const float*)d_in[2];
    const float* Wk = (const float*)d_in[3];
    const float* bk = (const float*)d_in[4];
    const float* Wv = (const float*)d_in[5];
    const float* bv = (const float*)d_in[6];
    float* out = (float*)d_out;

    reset_ctr_kernel<<<1, 1>>>();
    qkv_kernel<<<dim3(128, 3), 256>>>(x, Wq, bq, Wk, bk, Wv, bv);

    const int smem = 6 * 64 * 72 * (int)sizeof(__nv_bfloat16);   // 55296 B
    cudaFuncSetAttribute(attn_kernel,
                         cudaFuncAttributeMaxDynamicSharedMemorySize, smem);
    attn_kernel<<<592, 128, smem>>>();

    combine_kernel<<<256, 256>>>(out);
}